// round 13
// baseline (speedup 1.0000x reference)
#include <cuda_runtime.h>
#include <cuda_bf16.h>
#include <cstdint>

// Problem constants
#define BATCH 256
#define TT    512
#define DIN   128
#define DFEAT 256
#define DLAT  512
#define GG    2048
#define NBLK  128            // 4 batch-tiles x 32 gate-tiles, persistent, 1 CTA/SM
#define NTHR  256            // 8 warps = 2 K-split groups of 4
#define ENC_SLOTS 32

// ---------------- device-global scratch, MMA-fragment layout (~9 MB) --------
// h:   [buf][row_tile(16)][chunk(32)][lane(32)] uint4 {a0,a2,a1,a3}
// enc: [slot][row_tile(16)][chunk(16)][lane(32)] uint4 {a0,a2,a1,a3}
__device__ uint4 g_hfhi[2][16 * 32 * 32];            // 256 KB / buf
__device__ uint4 g_hflo[2][16 * 32 * 32];
__device__ uint4 g_encfhi[ENC_SLOTS][16 * 16 * 32];  // 4 MB
__device__ uint4 g_encflo[ENC_SLOTS][16 * 16 * 32];
__device__ unsigned g_flags[NBLK];                   // split-phase barrier flags

// ---------------- smem layout (bytes) ----------------
#define SM_WHI  0                        // W_h hi  [64 n][512 k] bf16, row=1024B
#define SM_WLO  65536
#define SM_XHI  131072                   // W_x hi  [64 n][256 k] bf16, row=512B
#define SM_XLO  163840
#define SM_ENC  196608                   // enc staging: hA 16*68 f32 + sB 16*64 f32 = 8448
#define SM_ZRED (SM_ENC + 8448)          // halves exchange [2][4][8][32] float2 = 16384
#define SM_BIAS (SM_ZRED + 16384)        // 64 floats
#define SM_TOTAL (SM_BIAS + 256)         // 221,696 B

// ---------------- math ----------------
__device__ __forceinline__ float sigmoidf_(float x) { return 1.0f / (1.0f + __expf(-x)); }
__device__ __forceinline__ float tanhf_(float x) {
    x = fminf(fmaxf(x, -12.0f), 12.0f);
    float e = __expf(2.0f * x);
    return (e - 1.0f) / (e + 1.0f);
}
__device__ __forceinline__ float b2f(uint32_t u) {
    unsigned short s = (unsigned short)u;
    __nv_bfloat16 b = *reinterpret_cast<__nv_bfloat16*>(&s);
    return __bfloat162float(b);
}

// ---------------- split-phase flag barrier (128 co-resident CTAs) -----------
// signal: own flag (distinct address -> parallel arrivals). wait: warp0 polls
// all 128 flags, 1 uint4 per lane. Monotonic counters; graph-replay safe.
__device__ __forceinline__ void bar_signal(unsigned target) {
    __threadfence();
    atomicExch(&g_flags[blockIdx.x], target);
}
__device__ __forceinline__ void bar_wait(unsigned target) {
    if (threadIdx.x < 32) {
        const uint4* f4 = reinterpret_cast<const uint4*>(g_flags);
        for (;;) {
            uint4 v = __ldcg(&f4[threadIdx.x]);
            bool ok = ((int)(v.x - target) >= 0) && ((int)(v.y - target) >= 0) &&
                      ((int)(v.z - target) >= 0) && ((int)(v.w - target) >= 0);
            if (__all_sync(0xFFFFFFFFu, ok)) break;
            __nanosleep(32);
        }
        __threadfence();
    }
    __syncthreads();
}

// ---------------- PTX helpers (baseline PTX, sm_80-era) ----------------
__device__ __forceinline__ uint32_t s2u(const void* p) {
    uint32_t a;
    asm("{ .reg .u64 t; cvta.to.shared.u64 t, %1; cvt.u32.u64 %0, t; }" : "=r"(a) : "l"(p));
    return a;
}
__device__ __forceinline__ void ldsm4(uint32_t& r0, uint32_t& r1, uint32_t& r2, uint32_t& r3,
                                      uint32_t addr) {
    asm volatile("ldmatrix.sync.aligned.m8n8.x4.shared.b16 {%0,%1,%2,%3}, [%4];"
                 : "=r"(r0), "=r"(r1), "=r"(r2), "=r"(r3) : "r"(addr));
}
__device__ __forceinline__ void mma4(float* d, const uint32_t* a, const uint32_t* b) {
    asm volatile(
        "mma.sync.aligned.m16n8k16.row.col.f32.bf16.bf16.f32 "
        "{%0,%1,%2,%3}, {%4,%5,%6,%7}, {%8,%9}, {%0,%1,%2,%3};"
        : "+f"(d[0]), "+f"(d[1]), "+f"(d[2]), "+f"(d[3])
        : "r"(a[0]), "r"(a[1]), "r"(a[2]), "r"(a[3]), "r"(b[0]), "r"(b[1]));
}

// ---------------- hi/lo split helper ----------------
__device__ __forceinline__ void split_bf16(float v, unsigned short& hi, unsigned short& lo) {
    __nv_bfloat16 h16 = __float2bfloat16(v);
    __nv_bfloat16 l16 = __float2bfloat16(v - __bfloat162float(h16));
    hi = __bfloat16_as_ushort(h16);
    lo = __bfloat16_as_ushort(l16);
}

// ---------------- MMA accumulate, fragment-layout A (2x LDG.128/chunk) ------
// acc += A(frag global hi/lo) @ B(smem hi/lo). NCH chunks (even), B chunk
// base cbase. Fragment memory order {a0,a2,a1,a3}: permuted on load.
// 3-pass: AhiBhi + AhiBlo + AloBhi. Hazard-safe double-buffered schedule.
template<int NCH>
__device__ __forceinline__ void mma_accF(
    float (&acc)[8][4],
    const uint4* __restrict__ aHiT, const uint4* __restrict__ aLoT,
    const uint32_t* bHiA, const uint32_t* bLoA,
    int cbase, int koff, int swz)
{
    uint32_t aH[2][4], aL[2][4];
    uint32_t bh[2][8][2], bl[2][8][2];

    auto loadA = [&](int buf, int c) {
        uint4 vh = aHiT[c * 32];
        uint4 vl = aLoT[c * 32];
        // memory {a0,a2,a1,a3} -> regs {a0,a1,a2,a3}
        aH[buf][0] = vh.x; aH[buf][1] = vh.z; aH[buf][2] = vh.y; aH[buf][3] = vh.w;
        aL[buf][0] = vl.x; aL[buf][1] = vl.z; aL[buf][2] = vl.y; aL[buf][3] = vl.w;
    };
    auto loadB = [&](int buf, int c) {
        const int off = ((cbase + c) * 32 + koff) ^ swz;
#pragma unroll
        for (int p = 0; p < 4; p++) {
            ldsm4(bh[buf][2 * p][0], bh[buf][2 * p][1],
                  bh[buf][2 * p + 1][0], bh[buf][2 * p + 1][1], bHiA[p] + off);
            ldsm4(bl[buf][2 * p][0], bl[buf][2 * p][1],
                  bl[buf][2 * p + 1][0], bl[buf][2 * p + 1][1], bLoA[p] + off);
        }
    };
    auto doMMA = [&](int buf) {
#pragma unroll
        for (int nt = 0; nt < 8; nt++) {
            mma4(acc[nt], aH[buf], bh[buf][nt]);
            mma4(acc[nt], aH[buf], bl[buf][nt]);
            mma4(acc[nt], aL[buf], bh[buf][nt]);
        }
    };

    loadA(0, 0);
    loadB(0, 0);
    loadA(1, 1);
#pragma unroll 1
    for (int c = 0; c < NCH; c += 2) {
        loadB(1, c + 1);
        doMMA(0);
        if (c + 2 < NCH) {
            loadA(0, c + 2);
            loadB(0, c + 2);
        }
        doMMA(1);
        if (c + 3 < NCH) loadA(1, c + 3);
    }
}

// ---------------- encoder FFMA phase (amortized /8 steps, 128 CTAs x 256 thr)
// 128 CTAs cover 8 timesteps x 4 batch-tiles(64) x 4 col-tiles(64). K=128.
// Output goes to the enc FRAGMENT layout ({a0,a2,a1,a3} order).
__device__ void enc_phase(
    char* smem, const float* __restrict__ x, const float* __restrict__ W_enc,
    const float* __restrict__ b_enc, int sbase, int bid, int tid)
{
    const int q = bid >> 2;
    const int s = sbase + (q >> 2);
    if (s >= TT) return;
    const int b0  = (q & 3) * 64;
    const int n0e = (bid & 3) * 64;
    const int tn = tid & 15, tm = tid >> 4;            // tm 0..15 (4 rows each)
    float* hA = reinterpret_cast<float*>(smem + SM_ENC);         // [16][68]
    float* sB = hA + 16 * 68;                                    // [16][64]

    float acc[4][4];
#pragma unroll
    for (int i = 0; i < 4; i++)
#pragma unroll
        for (int j = 0; j < 4; j++) acc[i][j] = 0.0f;

#pragma unroll 1
    for (int k0 = 0; k0 < DIN; k0 += 16) {
        {   // A^T: 64 rows x 16 k = 256 float4, one per thread
            int row = tid >> 2, kq = tid & 3;
            float4 v = *reinterpret_cast<const float4*>(
                &x[(size_t)(b0 + row) * TT * DIN + (size_t)s * DIN + k0 + kq * 4]);
            hA[(kq * 4 + 0) * 68 + row] = v.x; hA[(kq * 4 + 1) * 68 + row] = v.y;
            hA[(kq * 4 + 2) * 68 + row] = v.z; hA[(kq * 4 + 3) * 68 + row] = v.w;
        }
        {   // B: 16 x 64 = 256 float4, one per thread
            int kr = tid >> 4, nq = tid & 15;
            float4 v = *reinterpret_cast<const float4*>(
                &W_enc[(size_t)(k0 + kr) * DFEAT + n0e + nq * 4]);
            *reinterpret_cast<float4*>(&sB[kr * 64 + nq * 4]) = v;
        }
        __syncthreads();
#pragma unroll
        for (int k = 0; k < 16; k++) {
            float a[4], b[4];
            *reinterpret_cast<float4*>(&a[0]) = *reinterpret_cast<const float4*>(&hA[k * 68 + tm * 4]);
            *reinterpret_cast<float4*>(&b[0]) = *reinterpret_cast<const float4*>(&sB[k * 64 + tn * 4]);
#pragma unroll
            for (int i = 0; i < 4; i++)
#pragma unroll
                for (int j = 0; j < 4; j++) acc[i][j] = fmaf(a[i], b[j], acc[i][j]);
        }
        __syncthreads();
    }

    float bia[4];
    *reinterpret_cast<float4*>(&bia[0]) = *reinterpret_cast<const float4*>(&b_enc[n0e + tn * 4]);
    uint32_t* dhi = reinterpret_cast<uint32_t*>(g_encfhi[s & (ENC_SLOTS - 1)]);
    uint32_t* dlo = reinterpret_cast<uint32_t*>(g_encflo[s & (ENC_SLOTS - 1)]);
#pragma unroll
    for (int i = 0; i < 4; i++) {
        const int row = b0 + tm * 4 + i;
        const int row_tile = row >> 4, rr = row & 15;
        const int r = rr & 7, rowhalf = rr >> 3;
#pragma unroll
        for (int p = 0; p < 2; p++) {                 // col pair: 4tn+2p, +1
            const int col = n0e + tn * 4 + 2 * p;
            const int chunk = col >> 4, cc = col & 15;
            const int lane = (r << 2) | ((cc & 7) >> 1);
            const int reg = (rowhalf << 1) | (cc >> 3);  // {a0,a2,a1,a3} order
            float v0 = tanhf_(acc[i][2 * p]     + bia[2 * p]);
            float v1 = tanhf_(acc[i][2 * p + 1] + bia[2 * p + 1]);
            unsigned short h0, l0, h1, l1;
            split_bf16(v0, h0, l0);
            split_bf16(v1, h1, l1);
            size_t idx = ((((size_t)row_tile * 16 + chunk) * 32 + lane) << 2) + reg;
            dhi[idx] = (uint32_t)h0 | ((uint32_t)h1 << 16);
            dlo[idx] = (uint32_t)l0 | ((uint32_t)l1 << 16);
        }
    }
}

// ---------------- the fused persistent HMMA kernel (K-split, 8 warps) -------
__global__ void __launch_bounds__(NTHR, 1) lstm_hmma_kernel(
    const float* __restrict__ x, const float* __restrict__ W_enc,
    const float* __restrict__ b_enc, const float* __restrict__ W_x,
    const float* __restrict__ W_h, const float* __restrict__ b_lstm,
    const float* __restrict__ W_dec, const float* __restrict__ b_dec,
    float* __restrict__ out)
{
    extern __shared__ char smem[];
    const int tid = threadIdx.x;
    const int bid = blockIdx.x;
    const int lane = tid & 31;
    const int wid = tid >> 5;
    const int w4 = wid & 3;              // row slice within group
    const int wg = wid >> 2;             // K-split group (0 or 1)
    const int jb = bid & 31;             // gate tile (16 latent cols) == h chunk
    const int mb = bid >> 5;             // batch tile (64 rows)
    const int m0 = mb * 64, j0 = jb * 16;
    const int row_tile = 4 * mb + w4;    // this warp's 16-row group (0..15)
    const uint32_t smem_u = s2u(smem);
    float* biasS = reinterpret_cast<float*>(smem + SM_BIAS);
    float2* zRed = reinterpret_cast<float2*>(smem + SM_ZRED);  // [2][4][8][32]

    // ---- fill weight slices (bf16 hi/lo, [n][k] rows, XOR-swizzled) ----
    for (int idx = tid; idx < 64 * 512; idx += NTHR) {
        int n = idx >> 9, k = idx & 511;
        float w = W_h[(size_t)k * GG + (n >> 4) * DLAT + j0 + (n & 15)];
        unsigned short sh, sl;
        split_bf16(w, sh, sl);
        uint32_t off = (uint32_t)(n * 1024 + ((2 * k) ^ ((n & 7) << 4)));
        *reinterpret_cast<unsigned short*>(smem + SM_WHI + off) = sh;
        *reinterpret_cast<unsigned short*>(smem + SM_WLO + off) = sl;
    }
    for (int idx = tid; idx < 64 * 256; idx += NTHR) {
        int n = idx >> 8, k = idx & 255;
        float w = W_x[(size_t)k * GG + (n >> 4) * DLAT + j0 + (n & 15)];
        unsigned short sh, sl;
        split_bf16(w, sh, sl);
        uint32_t off = (uint32_t)(n * 512 + ((2 * k) ^ ((n & 7) << 4)));
        *reinterpret_cast<unsigned short*>(smem + SM_XHI + off) = sh;
        *reinterpret_cast<unsigned short*>(smem + SM_XLO + off) = sl;
    }
    if (tid < 64) biasS[tid] = b_lstm[(tid >> 4) * DLAT + j0 + (tid & 15)];

    // ---- per-lane geometry ----
    const int lm = lane >> 3, lr = lane & 7;
    const int koff = (lm & 1) * 16;                    // B klow/khigh select
    const int swz = lr << 4;                           // B swizzle
    uint32_t bW_hi[4], bW_lo[4], bX_hi[4], bX_lo[4];
#pragma unroll
    for (int p = 0; p < 4; p++) {
        int n = 16 * p + 8 * (lm >> 1) + lr;
        bW_hi[p] = smem_u + SM_WHI + n * 1024;
        bW_lo[p] = smem_u + SM_WLO + n * 1024;
        bX_hi[p] = smem_u + SM_XHI + n * 512;
        bX_lo[p] = smem_u + SM_XLO + n * 512;
    }
    const int jc = 2 * (lane & 3);

    // fragment pointers (this warp's row_tile, group chunk base, lane)
    const int hCB = 16 * wg;             // recurrent chunk base for this group
    const int xCB = 8 * wg;              // xz chunk base
    const uint4* hA0  = g_hfhi[0] + ((size_t)row_tile * 32 + hCB) * 32 + lane;
    const uint4* hA0l = g_hflo[0] + ((size_t)row_tile * 32 + hCB) * 32 + lane;
    const uint4* hA1  = g_hfhi[1] + ((size_t)row_tile * 32 + hCB) * 32 + lane;
    const uint4* hA1l = g_hflo[1] + ((size_t)row_tile * 32 + hCB) * 32 + lane;
    const size_t encOff = ((size_t)row_tile * 16 + xCB) * 32 + lane;
    const size_t hStoreIdx = ((size_t)row_tile * 32 + jb) * 32 + lane;

    // halves-exchange pointers: group g writes region g, reads region 1-g
    float2* zPub = zRed + (((size_t)wg * 4 + w4) * 8) * 32 + lane;
    const float2* zGet = zRed + (((size_t)(1 - wg) * 4 + w4) * 8) * 32 + lane;

    unsigned gen = *((volatile unsigned*)&g_flags[blockIdx.x]);
    float cReg[4];
#pragma unroll
    for (int i = 0; i < 4; i++) cReg[i] = 0.0f;
    float acc[8][4];

    // ---- prologue: enc slots [0,16); signal+wait; xz(0) partials ----
    __syncthreads();                                   // weights/bias visible
    enc_phase(smem, x, W_enc, b_enc, 0, bid, tid);
    enc_phase(smem, x, W_enc, b_enc, 8, bid, tid);
    __syncthreads();
    gen++;
    if (tid == 0) bar_signal(gen);
    bar_wait(gen);
#pragma unroll
    for (int i = 0; i < 8; i++)
#pragma unroll
        for (int j = 0; j < 4; j++) acc[i][j] = 0.0f;
    mma_accF<8>(acc, g_encfhi[0] + encOff, g_encflo[0] + encOff,
                bX_hi, bX_lo, xCB, koff, swz);

    // ---- main scan ----
#pragma unroll 1
    for (int t = 0; t < TT; t++) {
        // recurrent partial: acc += h(t) @ W_h[group k half]  (skip t=0)
        if (t > 0) {
            const uint4* ah = (t & 1) ? hA1 : hA0;
            const uint4* al = (t & 1) ? hA1l : hA0l;
            mma_accF<16>(acc, ah, al, bW_hi, bW_lo, hCB, koff, swz);
        }

        // symmetric exchange: group0 publishes rows r+8, group1 rows r
#pragma unroll
        for (int nt = 0; nt < 8; nt++)
            zPub[nt * 32] = (wg == 0) ? make_float2(acc[nt][2], acc[nt][3])
                                      : make_float2(acc[nt][0], acc[nt][1]);
        __syncthreads();

        // combine + epilogue: group0 -> rows r, group1 -> rows r+8 (4 cells)
        {
            float z[8][2];
#pragma unroll
            for (int nt = 0; nt < 8; nt++) {
                float2 v = zGet[nt * 32];
                z[nt][0] = acc[nt][2 * wg]     + v.x;
                z[nt][1] = acc[nt][2 * wg + 1] + v.y;
            }
            uint32_t PH[2], PL[2];
#pragma unroll
            for (int jhi = 0; jhi < 2; jhi++) {
                uint32_t packH = 0, packL = 0;
#pragma unroll
                for (int je = 0; je < 2; je++) {
                    const int j = 8 * jhi + jc + je;
                    float zi = z[0 + jhi][je] + biasS[j];
                    float zf = z[2 + jhi][je] + biasS[16 + j];
                    float zg = z[4 + jhi][je] + biasS[32 + j];
                    float zo = z[6 + jhi][je] + biasS[48 + j];
                    float ig = sigmoidf_(zi), fg = sigmoidf_(zf);
                    float gg = tanhf_(zg),   og = sigmoidf_(zo);
                    const int ci = jhi * 2 + je;
                    float cn = fg * cReg[ci] + ig * gg;
                    cReg[ci] = cn;
                    float hv = og * tanhf_(cn);
                    unsigned short sh, sl;
                    split_bf16(hv, sh, sl);
                    packH |= (uint32_t)sh << (16 * je);
                    packL |= (uint32_t)sl << (16 * je);
                }
                PH[jhi] = packH;
                PL[jhi] = packL;
            }
            // fragment slot {a0,a2,a1,a3}: group0 -> first uint2, group1 -> second
            uint2* oh = reinterpret_cast<uint2*>(g_hfhi[(t + 1) & 1] + hStoreIdx) + wg;
            uint2* ol = reinterpret_cast<uint2*>(g_hflo[(t + 1) & 1] + hStoreIdx) + wg;
            *oh = make_uint2(PH[0], PH[1]);
            *ol = make_uint2(PL[0], PL[1]);
        }

        // signal EARLY: h(t+1) is published; xz + enc overlap the propagation
        __syncthreads();
        gen++;
        if (tid == 0) bar_signal(gen);

        // encoder lookahead (all threads; internal syncthreads are uniform)
        if ((t & 7) == 0 && t + 16 < TT)
            enc_phase(smem, x, W_enc, b_enc, t + 16, bid, tid);

        // xz(t+1) partial into acc (overlaps other CTAs' barrier wait)
        if (t + 1 < TT) {
            const int slot = (t + 1) & (ENC_SLOTS - 1);
#pragma unroll
            for (int i = 0; i < 8; i++)
#pragma unroll
                for (int j = 0; j < 4; j++) acc[i][j] = 0.0f;
            mma_accF<8>(acc, g_encfhi[slot] + encOff, g_encflo[slot] + encOff,
                        bX_hi, bX_lo, xCB, koff, swz);
        }

        bar_wait(gen);                                 // h(t+1) visible everywhere
    }

    // ---- decoder: out[b] = h_last @ W_dec + b_dec (h_last in buf 0) ----
    if (jb == 0 && tid < 64) {
        const int row = m0 + tid;
        const int rt2 = row >> 4, rr = row & 15;
        const int r = rr & 7, rowhalf = rr >> 3;
        const uint32_t* hh = reinterpret_cast<const uint32_t*>(g_hfhi[0]);
        const uint32_t* hl = reinterpret_cast<const uint32_t*>(g_hflo[0]);
        float s = 0.0f;
        for (int k = 0; k < DLAT; k++) {
            const int chunk = k >> 4, cc = k & 15;
            const int ln = (r << 2) | ((cc & 7) >> 1);
            const int reg = (rowhalf << 1) | (cc >> 3);   // {a0,a2,a1,a3} order
            size_t idx = ((((size_t)rt2 * 32 + chunk) * 32 + ln) << 2) + reg;
            const int shf = (cc & 1) * 16;
            float hv = b2f(hh[idx] >> shf) + b2f(hl[idx] >> shf);
            s = fmaf(hv, W_dec[k], s);
        }
        out[row] = s + b_dec[0];
    }
}

// ---------------- eager module touch ----------------
namespace {
struct EagerLoad {
    EagerLoad() {
        void* p;
        cudaGetSymbolAddress(&p, g_encfhi);
        cudaGetSymbolAddress(&p, g_encflo);
        cudaGetSymbolAddress(&p, g_hfhi);
        cudaGetSymbolAddress(&p, g_hflo);
        cudaGetSymbolAddress(&p, g_flags);
        cudaFuncSetAttribute(lstm_hmma_kernel,
                             cudaFuncAttributeMaxDynamicSharedMemorySize, SM_TOTAL);
    }
};
EagerLoad eager_load_instance;
}  // namespace

// ---------------- launch ----------------
extern "C" void kernel_launch(void* const* d_in, const int* in_sizes, int n_in,
                              void* d_out, int out_size)
{
    const float* x      = (const float*)d_in[0];
    const float* W_enc  = (const float*)d_in[1];
    const float* b_enc  = (const float*)d_in[2];
    const float* W_x    = (const float*)d_in[3];
    const float* W_h    = (const float*)d_in[4];
    const float* b_lstm = (const float*)d_in[5];
    const float* W_dec  = (const float*)d_in[6];
    const float* b_dec  = (const float*)d_in[7];
    float* out = (float*)d_out;

    cudaFuncSetAttribute(lstm_hmma_kernel,
                         cudaFuncAttributeMaxDynamicSharedMemorySize, SM_TOTAL);

    lstm_hmma_kernel<<<NBLK, NTHR, SM_TOTAL>>>(
        x, W_enc, b_enc, W_x, W_h, b_lstm, W_dec, b_dec, out);
}

// round 14
// speedup vs baseline: 1.4211x; 1.4211x over previous
#include <cuda_runtime.h>
#include <cuda_bf16.h>
#include <cstdint>

// Problem constants
#define BATCH 256
#define TT    512
#define DIN   128
#define DFEAT 256
#define DLAT  512
#define GG    2048
#define NBLK  128            // 4 batch-tiles x 32 gate-tiles, persistent, 1 CTA/SM
#define NTHR  256            // 8 warps = 2 K-split groups of 4
#define ENC_SLOTS 32

// ---------------- device-global scratch, MMA-fragment layout (~9 MB) --------
// h:   [buf][row_tile(16)][chunk(32)][lane(32)] uint4 {R0,R1,R2,R3}
// enc: [slot][row_tile(16)][chunk(16)][lane(32)] uint4
__device__ uint4 g_hfhi[2][16 * 32 * 32];            // 256 KB / buf
__device__ uint4 g_hflo[2][16 * 32 * 32];
__device__ uint4 g_encfhi[ENC_SLOTS][16 * 16 * 32];  // 4 MB
__device__ uint4 g_encflo[ENC_SLOTS][16 * 16 * 32];
__device__ unsigned g_bar_cnt;
__device__ unsigned g_bar_gen;

// ---------------- smem layout (bytes) ----------------
#define SM_WHI  0                        // W_h hi  [64 n][512 k] bf16, row=1024B
#define SM_WLO  65536
#define SM_XHI  131072                   // W_x hi  [64 n][256 k] bf16, row=512B
#define SM_XLO  163840
#define SM_ENC  196608                   // enc staging: hA 16*68 f32 + sB 16*64 f32 = 8448
#define SM_ZRED (SM_ENC + 8448)          // K-split reduction [4][8][32] float4 = 16384
#define SM_BIAS (SM_ZRED + 16384)        // 64 floats
#define SM_TOTAL (SM_BIAS + 256)         // 221,696 B

// ---------------- math ----------------
__device__ __forceinline__ float sigmoidf_(float x) { return 1.0f / (1.0f + __expf(-x)); }
__device__ __forceinline__ float tanhf_(float x) {
    x = fminf(fmaxf(x, -12.0f), 12.0f);
    float e = __expf(2.0f * x);
    return (e - 1.0f) / (e + 1.0f);
}
__device__ __forceinline__ float b2f(uint32_t u) {
    unsigned short s = (unsigned short)u;
    __nv_bfloat16 b = *reinterpret_cast<__nv_bfloat16*>(&s);
    return __bfloat162float(b);
}

// ---------------- split-phase central barrier (128 co-resident CTAs) --------
// arrive: one atomicAdd per CTA; last arriver resets counter and bumps gen.
// wait: thread0 spins on gen (single address, 1 thread/CTA). Identical L2
// traffic to the R12 fused barrier; just decoupled so work fits in between.
__device__ __forceinline__ void bar_arrive(unsigned gen) {
    __threadfence();
    unsigned arrived = atomicAdd(&g_bar_cnt, 1u);
    if (arrived == NBLK - 1) {
        atomicExch(&g_bar_cnt, 0u);
        __threadfence();
        *((volatile unsigned*)&g_bar_gen) = gen + 1u;
    }
}
__device__ __forceinline__ void bar_spin(unsigned gen) {
    while (*((volatile unsigned*)&g_bar_gen) == gen) { __nanosleep(32); }
    __threadfence();
}

// ---------------- PTX helpers (baseline PTX, sm_80-era) ----------------
__device__ __forceinline__ uint32_t s2u(const void* p) {
    uint32_t a;
    asm("{ .reg .u64 t; cvta.to.shared.u64 t, %1; cvt.u32.u64 %0, t; }" : "=r"(a) : "l"(p));
    return a;
}
__device__ __forceinline__ void ldsm4(uint32_t& r0, uint32_t& r1, uint32_t& r2, uint32_t& r3,
                                      uint32_t addr) {
    asm volatile("ldmatrix.sync.aligned.m8n8.x4.shared.b16 {%0,%1,%2,%3}, [%4];"
                 : "=r"(r0), "=r"(r1), "=r"(r2), "=r"(r3) : "r"(addr));
}
__device__ __forceinline__ void mma4(float* d, const uint32_t* a, const uint32_t* b) {
    asm volatile(
        "mma.sync.aligned.m16n8k16.row.col.f32.bf16.bf16.f32 "
        "{%0,%1,%2,%3}, {%4,%5,%6,%7}, {%8,%9}, {%0,%1,%2,%3};"
        : "+f"(d[0]), "+f"(d[1]), "+f"(d[2]), "+f"(d[3])
        : "r"(a[0]), "r"(a[1]), "r"(a[2]), "r"(a[3]), "r"(b[0]), "r"(b[1]));
}

// ---------------- hi/lo split helper ----------------
__device__ __forceinline__ void split_bf16(float v, unsigned short& hi, unsigned short& lo) {
    __nv_bfloat16 h16 = __float2bfloat16(v);
    __nv_bfloat16 l16 = __float2bfloat16(v - __bfloat162float(h16));
    hi = __bfloat16_as_ushort(h16);
    lo = __bfloat16_as_ushort(l16);
}

// ---------------- MMA accumulate, fragment-layout A (2x LDG.128/chunk) ------
// acc += A(frag global hi/lo) @ B(smem hi/lo). NCH chunks (even), B chunk
// base cbase. aHiT/aLoT already offset by (row_tile, group chunk base, lane).
// 3-pass: AhiBhi + AhiBlo + AloBhi. Hazard-safe double-buffered schedule.
template<int NCH>
__device__ __forceinline__ void mma_accF(
    float (&acc)[8][4],
    const uint4* __restrict__ aHiT, const uint4* __restrict__ aLoT,
    const uint32_t* bHiA, const uint32_t* bLoA,
    int cbase, int koff, int swz)
{
    uint32_t aH[2][4], aL[2][4];
    uint32_t bh[2][8][2], bl[2][8][2];

    auto loadA = [&](int buf, int c) {
        uint4 vh = aHiT[c * 32];
        uint4 vl = aLoT[c * 32];
        aH[buf][0] = vh.x; aH[buf][1] = vh.y; aH[buf][2] = vh.z; aH[buf][3] = vh.w;
        aL[buf][0] = vl.x; aL[buf][1] = vl.y; aL[buf][2] = vl.z; aL[buf][3] = vl.w;
    };
    auto loadB = [&](int buf, int c) {
        const int off = ((cbase + c) * 32 + koff) ^ swz;
#pragma unroll
        for (int p = 0; p < 4; p++) {
            ldsm4(bh[buf][2 * p][0], bh[buf][2 * p][1],
                  bh[buf][2 * p + 1][0], bh[buf][2 * p + 1][1], bHiA[p] + off);
            ldsm4(bl[buf][2 * p][0], bl[buf][2 * p][1],
                  bl[buf][2 * p + 1][0], bl[buf][2 * p + 1][1], bLoA[p] + off);
        }
    };
    auto doMMA = [&](int buf) {
#pragma unroll
        for (int nt = 0; nt < 8; nt++) {
            mma4(acc[nt], aH[buf], bh[buf][nt]);
            mma4(acc[nt], aH[buf], bl[buf][nt]);
            mma4(acc[nt], aL[buf], bh[buf][nt]);
        }
    };

    loadA(0, 0);
    loadB(0, 0);
    loadA(1, 1);
#pragma unroll 1
    for (int c = 0; c < NCH; c += 2) {
        loadB(1, c + 1);
        doMMA(0);
        if (c + 2 < NCH) {
            loadA(0, c + 2);
            loadB(0, c + 2);
        }
        doMMA(1);
        if (c + 3 < NCH) loadA(1, c + 3);
    }
}

// ---------------- encoder FFMA phase (amortized /8 steps, 128 CTAs x 256 thr)
// 128 CTAs cover 8 timesteps x 4 batch-tiles(64) x 4 col-tiles(64). K=128.
// Output goes to the enc FRAGMENT layout.
__device__ void enc_phase(
    char* smem, const float* __restrict__ x, const float* __restrict__ W_enc,
    const float* __restrict__ b_enc, int sbase, int bid, int tid)
{
    const int q = bid >> 2;
    const int s = sbase + (q >> 2);
    if (s >= TT) return;
    const int b0  = (q & 3) * 64;
    const int n0e = (bid & 3) * 64;
    const int tn = tid & 15, tm = tid >> 4;            // tm 0..15 (4 rows each)
    float* hA = reinterpret_cast<float*>(smem + SM_ENC);         // [16][68]
    float* sB = hA + 16 * 68;                                    // [16][64]

    float acc[4][4];
#pragma unroll
    for (int i = 0; i < 4; i++)
#pragma unroll
        for (int j = 0; j < 4; j++) acc[i][j] = 0.0f;

#pragma unroll 1
    for (int k0 = 0; k0 < DIN; k0 += 16) {
        {   // A^T: 64 rows x 16 k = 256 float4, one per thread
            int row = tid >> 2, kq = tid & 3;
            float4 v = *reinterpret_cast<const float4*>(
                &x[(size_t)(b0 + row) * TT * DIN + (size_t)s * DIN + k0 + kq * 4]);
            hA[(kq * 4 + 0) * 68 + row] = v.x; hA[(kq * 4 + 1) * 68 + row] = v.y;
            hA[(kq * 4 + 2) * 68 + row] = v.z; hA[(kq * 4 + 3) * 68 + row] = v.w;
        }
        {   // B: 16 x 64 = 256 float4, one per thread
            int kr = tid >> 4, nq = tid & 15;
            float4 v = *reinterpret_cast<const float4*>(
                &W_enc[(size_t)(k0 + kr) * DFEAT + n0e + nq * 4]);
            *reinterpret_cast<float4*>(&sB[kr * 64 + nq * 4]) = v;
        }
        __syncthreads();
#pragma unroll
        for (int k = 0; k < 16; k++) {
            float a[4], b[4];
            *reinterpret_cast<float4*>(&a[0]) = *reinterpret_cast<const float4*>(&hA[k * 68 + tm * 4]);
            *reinterpret_cast<float4*>(&b[0]) = *reinterpret_cast<const float4*>(&sB[k * 64 + tn * 4]);
#pragma unroll
            for (int i = 0; i < 4; i++)
#pragma unroll
                for (int j = 0; j < 4; j++) acc[i][j] = fmaf(a[i], b[j], acc[i][j]);
        }
        __syncthreads();
    }

    float bia[4];
    *reinterpret_cast<float4*>(&bia[0]) = *reinterpret_cast<const float4*>(&b_enc[n0e + tn * 4]);
    uint32_t* dhi = reinterpret_cast<uint32_t*>(g_encfhi[s & (ENC_SLOTS - 1)]);
    uint32_t* dlo = reinterpret_cast<uint32_t*>(g_encflo[s & (ENC_SLOTS - 1)]);
#pragma unroll
    for (int i = 0; i < 4; i++) {
        const int row = b0 + tm * 4 + i;
        const int row_tile = row >> 4, rr = row & 15;
        const int r = rr & 7, regbase = rr >> 3;
#pragma unroll
        for (int p = 0; p < 2; p++) {                 // col pair: 4tn+2p, +1
            const int col = n0e + tn * 4 + 2 * p;
            const int chunk = col >> 4, cc = col & 15;
            const int lane = (r << 2) | ((cc & 7) >> 1);
            const int reg = regbase | ((cc >> 3) << 1);
            float v0 = tanhf_(acc[i][2 * p]     + bia[2 * p]);
            float v1 = tanhf_(acc[i][2 * p + 1] + bia[2 * p + 1]);
            unsigned short h0, l0, h1, l1;
            split_bf16(v0, h0, l0);
            split_bf16(v1, h1, l1);
            size_t idx = ((((size_t)row_tile * 16 + chunk) * 32 + lane) << 2) + reg;
            dhi[idx] = (uint32_t)h0 | ((uint32_t)h1 << 16);
            dlo[idx] = (uint32_t)l0 | ((uint32_t)l1 << 16);
        }
    }
}

// ---------------- the fused persistent HMMA kernel (K-split, 8 warps) -------
__global__ void __launch_bounds__(NTHR, 1) lstm_hmma_kernel(
    const float* __restrict__ x, const float* __restrict__ W_enc,
    const float* __restrict__ b_enc, const float* __restrict__ W_x,
    const float* __restrict__ W_h, const float* __restrict__ b_lstm,
    const float* __restrict__ W_dec, const float* __restrict__ b_dec,
    float* __restrict__ out)
{
    extern __shared__ char smem[];
    const int tid = threadIdx.x;
    const int bid = blockIdx.x;
    const int lane = tid & 31;
    const int wid = tid >> 5;
    const int w4 = wid & 3;              // row slice within group
    const int wg = wid >> 2;             // K-split group (0 or 1)
    const int jb = bid & 31;             // gate tile (16 latent cols) == h chunk
    const int mb = bid >> 5;             // batch tile (64 rows)
    const int m0 = mb * 64, j0 = jb * 16;
    const int row_tile = 4 * mb + w4;    // this warp's 16-row group (0..15)
    const uint32_t smem_u = s2u(smem);
    float* biasS = reinterpret_cast<float*>(smem + SM_BIAS);
    float4* zRed = reinterpret_cast<float4*>(smem + SM_ZRED);  // [4][8][32]

    // ---- fill weight slices (bf16 hi/lo, [n][k] rows, XOR-swizzled) ----
    for (int idx = tid; idx < 64 * 512; idx += NTHR) {
        int n = idx >> 9, k = idx & 511;
        float w = W_h[(size_t)k * GG + (n >> 4) * DLAT + j0 + (n & 15)];
        unsigned short sh, sl;
        split_bf16(w, sh, sl);
        uint32_t off = (uint32_t)(n * 1024 + ((2 * k) ^ ((n & 7) << 4)));
        *reinterpret_cast<unsigned short*>(smem + SM_WHI + off) = sh;
        *reinterpret_cast<unsigned short*>(smem + SM_WLO + off) = sl;
    }
    for (int idx = tid; idx < 64 * 256; idx += NTHR) {
        int n = idx >> 8, k = idx & 255;
        float w = W_x[(size_t)k * GG + (n >> 4) * DLAT + j0 + (n & 15)];
        unsigned short sh, sl;
        split_bf16(w, sh, sl);
        uint32_t off = (uint32_t)(n * 512 + ((2 * k) ^ ((n & 7) << 4)));
        *reinterpret_cast<unsigned short*>(smem + SM_XHI + off) = sh;
        *reinterpret_cast<unsigned short*>(smem + SM_XLO + off) = sl;
    }
    if (tid < 64) biasS[tid] = b_lstm[(tid >> 4) * DLAT + j0 + (tid & 15)];

    // ---- per-lane geometry ----
    const int lm = lane >> 3, lr = lane & 7;
    const int koff = (lm & 1) * 16;                    // B klow/khigh select
    const int swz = lr << 4;                           // B swizzle
    uint32_t bW_hi[4], bW_lo[4], bX_hi[4], bX_lo[4];
#pragma unroll
    for (int p = 0; p < 4; p++) {
        int n = 16 * p + 8 * (lm >> 1) + lr;
        bW_hi[p] = smem_u + SM_WHI + n * 1024;
        bW_lo[p] = smem_u + SM_WLO + n * 1024;
        bX_hi[p] = smem_u + SM_XHI + n * 512;
        bX_lo[p] = smem_u + SM_XLO + n * 512;
    }
    const int jc = 2 * (lane & 3);

    // fragment pointers (this warp's row_tile, group chunk base, lane)
    const int hCB = 16 * wg;             // recurrent chunk base for this group
    const int xCB = 8 * wg;              // xz chunk base
    const uint4* hA0  = g_hfhi[0] + ((size_t)row_tile * 32 + hCB) * 32 + lane;
    const uint4* hA0l = g_hflo[0] + ((size_t)row_tile * 32 + hCB) * 32 + lane;
    const uint4* hA1  = g_hfhi[1] + ((size_t)row_tile * 32 + hCB) * 32 + lane;
    const uint4* hA1l = g_hflo[1] + ((size_t)row_tile * 32 + hCB) * 32 + lane;
    const size_t encOff = ((size_t)row_tile * 16 + xCB) * 32 + lane;
    const size_t hStoreIdx = ((size_t)row_tile * 32 + jb) * 32 + lane;

    unsigned gen = *((volatile unsigned*)&g_bar_gen);
    float cReg[8];
#pragma unroll
    for (int i = 0; i < 8; i++) cReg[i] = 0.0f;
    float acc[8][4];

    // ---- prologue: enc slots [0,16); barrier; xz(0) partials ----
    __syncthreads();                                   // weights/bias visible
    enc_phase(smem, x, W_enc, b_enc, 0, bid, tid);
    enc_phase(smem, x, W_enc, b_enc, 8, bid, tid);
    __syncthreads();
    if (tid == 0) bar_arrive(gen);
    if (tid == 0) bar_spin(gen);
    gen++;
    __syncthreads();
#pragma unroll
    for (int i = 0; i < 8; i++)
#pragma unroll
        for (int j = 0; j < 4; j++) acc[i][j] = 0.0f;
    mma_accF<8>(acc, g_encfhi[0] + encOff, g_encflo[0] + encOff,
                bX_hi, bX_lo, xCB, koff, swz);

    // ---- main scan ----
#pragma unroll 1
    for (int t = 0; t < TT; t++) {
        // recurrent partial: acc += h(t) @ W_h[group k half]  (skip t=0)
        if (t > 0) {
            const uint4* ah = (t & 1) ? hA1 : hA0;
            const uint4* al = (t & 1) ? hA1l : hA0l;
            mma_accF<16>(acc, ah, al, bW_hi, bW_lo, hCB, koff, swz);
        }

        // K-split reduction: group1 publishes partials, group0 combines
        if (wg == 1) {
#pragma unroll
            for (int nt = 0; nt < 8; nt++)
                zRed[(w4 * 8 + nt) * 32 + lane] =
                    make_float4(acc[nt][0], acc[nt][1], acc[nt][2], acc[nt][3]);
        }
        __syncthreads();

        if (wg == 0) {
            // combine + epilogue: gates -> c, h(t+1); h stored as uint4 frag
#pragma unroll
            for (int nt = 0; nt < 8; nt++) {
                float4 v = zRed[(w4 * 8 + nt) * 32 + lane];
                acc[nt][0] += v.x; acc[nt][1] += v.y;
                acc[nt][2] += v.z; acc[nt][3] += v.w;
            }
            uint32_t RH[4], RL[4];
#pragma unroll
            for (int jhi = 0; jhi < 2; jhi++) {
#pragma unroll
                for (int rs = 0; rs < 2; rs++) {
                    uint32_t packH = 0, packL = 0;
#pragma unroll
                    for (int je = 0; je < 2; je++) {
                        const int j = 8 * jhi + jc + je;
                        float zi = acc[0 + jhi][2 * rs + je] + biasS[j];
                        float zf = acc[2 + jhi][2 * rs + je] + biasS[16 + j];
                        float zg = acc[4 + jhi][2 * rs + je] + biasS[32 + j];
                        float zo = acc[6 + jhi][2 * rs + je] + biasS[48 + j];
                        float ig = sigmoidf_(zi), fg = sigmoidf_(zf);
                        float gg = tanhf_(zg),   og = sigmoidf_(zo);
                        const int ci = rs * 4 + jhi * 2 + je;
                        float cn = fg * cReg[ci] + ig * gg;
                        cReg[ci] = cn;
                        float hv = og * tanhf_(cn);
                        unsigned short sh, sl;
                        split_bf16(hv, sh, sl);
                        packH |= (uint32_t)sh << (16 * je);
                        packL |= (uint32_t)sl << (16 * je);
                    }
                    RH[rs + 2 * jhi] = packH;
                    RL[rs + 2 * jhi] = packL;
                }
            }
            uint4* oh = g_hfhi[(t + 1) & 1] + hStoreIdx;
            uint4* ol = g_hflo[(t + 1) & 1] + hStoreIdx;
            *oh = make_uint4(RH[0], RH[1], RH[2], RH[3]);
            *ol = make_uint4(RL[0], RL[1], RL[2], RL[3]);
        }

        // ARRIVE EARLY: h(t+1) stored; enc + xz below overlap the barrier
        __syncthreads();
        if (tid == 0) bar_arrive(gen);

        // encoder lookahead (all threads; internal syncthreads are uniform)
        if ((t & 7) == 0 && t + 16 < TT)
            enc_phase(smem, x, W_enc, b_enc, t + 16, bid, tid);

        // xz(t+1) partial into acc (overlaps barrier propagation)
        if (t + 1 < TT) {
            const int slot = (t + 1) & (ENC_SLOTS - 1);
#pragma unroll
            for (int i = 0; i < 8; i++)
#pragma unroll
                for (int j = 0; j < 4; j++) acc[i][j] = 0.0f;
            mma_accF<8>(acc, g_encfhi[slot] + encOff, g_encflo[slot] + encOff,
                        bX_hi, bX_lo, xCB, koff, swz);
        }

        // WAIT: h(t+1) visible everywhere before next recurrent GEMM
        if (tid == 0) bar_spin(gen);
        gen++;
        __syncthreads();
    }

    // ---- decoder: out[b] = h_last @ W_dec + b_dec (h_last in buf 0) ----
    if (jb == 0 && tid < 64) {
        const int row = m0 + tid;
        const int rt2 = row >> 4, rr = row & 15;
        const int r = rr & 7, regbase = rr >> 3;
        const uint32_t* hh = reinterpret_cast<const uint32_t*>(g_hfhi[0]);
        const uint32_t* hl = reinterpret_cast<const uint32_t*>(g_hflo[0]);
        float s = 0.0f;
        for (int k = 0; k < DLAT; k++) {
            const int chunk = k >> 4, cc = k & 15;
            const int ln = (r << 2) | ((cc & 7) >> 1);
            const int reg = regbase | ((cc >> 3) << 1);
            size_t idx = ((((size_t)rt2 * 32 + chunk) * 32 + ln) << 2) + reg;
            const int shf = (cc & 1) * 16;
            float hv = b2f(hh[idx] >> shf) + b2f(hl[idx] >> shf);
            s = fmaf(hv, W_dec[k], s);
        }
        out[row] = s + b_dec[0];
    }
}

// ---------------- eager module touch ----------------
namespace {
struct EagerLoad {
    EagerLoad() {
        void* p;
        cudaGetSymbolAddress(&p, g_encfhi);
        cudaGetSymbolAddress(&p, g_encflo);
        cudaGetSymbolAddress(&p, g_hfhi);
        cudaGetSymbolAddress(&p, g_hflo);
        cudaGetSymbolAddress(&p, g_bar_cnt);
        cudaFuncSetAttribute(lstm_hmma_kernel,
                             cudaFuncAttributeMaxDynamicSharedMemorySize, SM_TOTAL);
    }
};
EagerLoad eager_load_instance;
}  // namespace

// ---------------- launch ----------------
extern "C" void kernel_launch(void* const* d_in, const int* in_sizes, int n_in,
                              void* d_out, int out_size)
{
    const float* x      = (const float*)d_in[0];
    const float* W_enc  = (const float*)d_in[1];
    const float* b_enc  = (const float*)d_in[2];
    const float* W_x    = (const float*)d_in[3];
    const float* W_h    = (const float*)d_in[4];
    const float* b_lstm = (const float*)d_in[5];
    const float* W_dec  = (const float*)d_in[6];
    const float* b_dec  = (const float*)d_in[7];
    float* out = (float*)d_out;

    cudaFuncSetAttribute(lstm_hmma_kernel,
                         cudaFuncAttributeMaxDynamicSharedMemorySize, SM_TOTAL);

    lstm_hmma_kernel<<<NBLK, NTHR, SM_TOTAL>>>(
        x, W_enc, b_enc, W_x, W_h, b_lstm, W_dec, b_dec, out);
}

// round 15
// speedup vs baseline: 1.6179x; 1.1385x over previous
#include <cuda_runtime.h>
#include <cuda_bf16.h>
#include <cstdint>

// Problem constants
#define BATCH 256
#define TT    512
#define DIN   128
#define DFEAT 256
#define DLAT  512
#define GG    2048
#define NBLK  128            // 4 batch-tiles x 32 gate-tiles, persistent, 1 CTA/SM
#define NTHR  256            // 8 warps = 2 K-split groups of 4
#define ENC_SLOTS 32

// ---------------- device-global scratch, MMA-fragment layout (~9 MB) --------
// h:   [buf][row_tile(16)][chunk(32)][lane(32)] uint4 {R0,R1,R2,R3}
// enc: [slot][row_tile(16)][chunk(16)][lane(32)] uint4
__device__ uint4 g_hfhi[2][16 * 32 * 32];            // 256 KB / buf
__device__ uint4 g_hflo[2][16 * 32 * 32];
__device__ uint4 g_encfhi[ENC_SLOTS][16 * 16 * 32];  // 4 MB
__device__ uint4 g_encflo[ENC_SLOTS][16 * 16 * 32];
__device__ unsigned g_bar_cnt;
__device__ unsigned g_bar_gen;

// ---------------- smem layout (bytes) ----------------
#define SM_WHI  0                        // W_h hi  [64 n][512 k] bf16, row=1024B
#define SM_WLO  65536
#define SM_XHI  131072                   // W_x hi  [64 n][256 k] bf16, row=512B
#define SM_XLO  163840
#define SM_ENC  196608                   // enc staging: hA 16*68 f32 + sB 16*64 f32 = 8448
#define SM_ZRED (SM_ENC + 8448)          // K-split reduction [4][8][32] float4 = 16384
#define SM_BIAS (SM_ZRED + 16384)        // 64 floats
#define SM_TOTAL (SM_BIAS + 256)         // 221,696 B

// ---------------- math ----------------
__device__ __forceinline__ float sigmoidf_(float x) { return 1.0f / (1.0f + __expf(-x)); }
__device__ __forceinline__ float tanhf_(float x) {
    x = fminf(fmaxf(x, -12.0f), 12.0f);
    float e = __expf(2.0f * x);
    return (e - 1.0f) / (e + 1.0f);
}
__device__ __forceinline__ float b2f(uint32_t u) {
    unsigned short s = (unsigned short)u;
    __nv_bfloat16 b = *reinterpret_cast<__nv_bfloat16*>(&s);
    return __bfloat162float(b);
}

// ---------------- split-phase central barrier (128 co-resident CTAs) --------
__device__ __forceinline__ void bar_arrive(unsigned gen) {
    __threadfence();
    unsigned arrived = atomicAdd(&g_bar_cnt, 1u);
    if (arrived == NBLK - 1) {
        atomicExch(&g_bar_cnt, 0u);
        __threadfence();
        *((volatile unsigned*)&g_bar_gen) = gen + 1u;
    }
}
__device__ __forceinline__ void bar_spin(unsigned gen) {
    while (*((volatile unsigned*)&g_bar_gen) == gen) { __nanosleep(32); }
    __threadfence();
}

// ---------------- PTX helpers (baseline PTX, sm_80-era) ----------------
__device__ __forceinline__ uint32_t s2u(const void* p) {
    uint32_t a;
    asm("{ .reg .u64 t; cvta.to.shared.u64 t, %1; cvt.u32.u64 %0, t; }" : "=r"(a) : "l"(p));
    return a;
}
__device__ __forceinline__ void ldsm4(uint32_t& r0, uint32_t& r1, uint32_t& r2, uint32_t& r3,
                                      uint32_t addr) {
    asm volatile("ldmatrix.sync.aligned.m8n8.x4.shared.b16 {%0,%1,%2,%3}, [%4];"
                 : "=r"(r0), "=r"(r1), "=r"(r2), "=r"(r3) : "r"(addr));
}
__device__ __forceinline__ void mma4(float* d, const uint32_t* a, const uint32_t* b) {
    asm volatile(
        "mma.sync.aligned.m16n8k16.row.col.f32.bf16.bf16.f32 "
        "{%0,%1,%2,%3}, {%4,%5,%6,%7}, {%8,%9}, {%0,%1,%2,%3};"
        : "+f"(d[0]), "+f"(d[1]), "+f"(d[2]), "+f"(d[3])
        : "r"(a[0]), "r"(a[1]), "r"(a[2]), "r"(a[3]), "r"(b[0]), "r"(b[1]));
}

// ---------------- hi/lo split helper ----------------
__device__ __forceinline__ void split_bf16(float v, unsigned short& hi, unsigned short& lo) {
    __nv_bfloat16 h16 = __float2bfloat16(v);
    __nv_bfloat16 l16 = __float2bfloat16(v - __bfloat162float(h16));
    hi = __bfloat16_as_ushort(h16);
    lo = __bfloat16_as_ushort(l16);
}

// ---------------- MMA accumulate, fragment-layout A, QUAD-buffered A --------
// acc += A(frag global hi/lo) @ B(smem hi/lo). NCH chunks (multiple of 4).
// A prefetch distance 4 (covers L2 ~600cyc); B double-buffered (smem).
// 3-pass: AhiBhi + AhiBlo + AloBhi. Buffers refilled only AFTER consumption.
template<int NCH>
__device__ __forceinline__ void mma_accF(
    float (&acc)[8][4],
    const uint4* __restrict__ aHiT, const uint4* __restrict__ aLoT,
    const uint32_t* bHiA, const uint32_t* bLoA,
    int cbase, int koff, int swz)
{
    uint32_t aH[4][4], aL[4][4];
    uint32_t bh[2][8][2], bl[2][8][2];

    auto loadA = [&](int buf, int c) {
        uint4 vh = aHiT[c * 32];
        uint4 vl = aLoT[c * 32];
        aH[buf][0] = vh.x; aH[buf][1] = vh.y; aH[buf][2] = vh.z; aH[buf][3] = vh.w;
        aL[buf][0] = vl.x; aL[buf][1] = vl.y; aL[buf][2] = vl.z; aL[buf][3] = vl.w;
    };
    auto loadB = [&](int buf, int c) {
        const int off = ((cbase + c) * 32 + koff) ^ swz;
#pragma unroll
        for (int p = 0; p < 4; p++) {
            ldsm4(bh[buf][2 * p][0], bh[buf][2 * p][1],
                  bh[buf][2 * p + 1][0], bh[buf][2 * p + 1][1], bHiA[p] + off);
            ldsm4(bl[buf][2 * p][0], bl[buf][2 * p][1],
                  bl[buf][2 * p + 1][0], bl[buf][2 * p + 1][1], bLoA[p] + off);
        }
    };
    auto doMMA = [&](int buf, int bbuf) {
#pragma unroll
        for (int nt = 0; nt < 8; nt++) {
            mma4(acc[nt], aH[buf], bh[bbuf][nt]);
            mma4(acc[nt], aH[buf], bl[bbuf][nt]);
            mma4(acc[nt], aL[buf], bh[bbuf][nt]);
        }
    };

    loadA(0, 0); loadA(1, 1); loadA(2, 2); loadA(3, 3);
    loadB(0, 0);
#pragma unroll 1
    for (int c = 0; c < NCH; c += 4) {
        loadB(1, c + 1);
        doMMA(0, 0);                         // chunk c
        if (c + 4 < NCH) loadA(0, c + 4);    // refill AFTER consumption, dist 4
        loadB(0, c + 2);
        doMMA(1, 1);                         // chunk c+1
        if (c + 5 < NCH) loadA(1, c + 5);
        loadB(1, c + 3);
        doMMA(2, 0);                         // chunk c+2
        if (c + 6 < NCH) loadA(2, c + 6);
        if (c + 4 < NCH) loadB(0, c + 4);
        doMMA(3, 1);                         // chunk c+3
        if (c + 7 < NCH) loadA(3, c + 7);
    }
}

// ---------------- encoder FFMA phase (amortized /8 steps, 128 CTAs x 256 thr)
// 128 CTAs cover 8 timesteps x 4 batch-tiles(64) x 4 col-tiles(64). K=128.
// Output goes to the enc FRAGMENT layout.
__device__ void enc_phase(
    char* smem, const float* __restrict__ x, const float* __restrict__ W_enc,
    const float* __restrict__ b_enc, int sbase, int bid, int tid)
{
    const int q = bid >> 2;
    const int s = sbase + (q >> 2);
    if (s >= TT) return;
    const int b0  = (q & 3) * 64;
    const int n0e = (bid & 3) * 64;
    const int tn = tid & 15, tm = tid >> 4;            // tm 0..15 (4 rows each)
    float* hA = reinterpret_cast<float*>(smem + SM_ENC);         // [16][68]
    float* sB = hA + 16 * 68;                                    // [16][64]

    float acc[4][4];
#pragma unroll
    for (int i = 0; i < 4; i++)
#pragma unroll
        for (int j = 0; j < 4; j++) acc[i][j] = 0.0f;

#pragma unroll 1
    for (int k0 = 0; k0 < DIN; k0 += 16) {
        {   // A^T: 64 rows x 16 k = 256 float4, one per thread
            int row = tid >> 2, kq = tid & 3;
            float4 v = *reinterpret_cast<const float4*>(
                &x[(size_t)(b0 + row) * TT * DIN + (size_t)s * DIN + k0 + kq * 4]);
            hA[(kq * 4 + 0) * 68 + row] = v.x; hA[(kq * 4 + 1) * 68 + row] = v.y;
            hA[(kq * 4 + 2) * 68 + row] = v.z; hA[(kq * 4 + 3) * 68 + row] = v.w;
        }
        {   // B: 16 x 64 = 256 float4, one per thread
            int kr = tid >> 4, nq = tid & 15;
            float4 v = *reinterpret_cast<const float4*>(
                &W_enc[(size_t)(k0 + kr) * DFEAT + n0e + nq * 4]);
            *reinterpret_cast<float4*>(&sB[kr * 64 + nq * 4]) = v;
        }
        __syncthreads();
#pragma unroll
        for (int k = 0; k < 16; k++) {
            float a[4], b[4];
            *reinterpret_cast<float4*>(&a[0]) = *reinterpret_cast<const float4*>(&hA[k * 68 + tm * 4]);
            *reinterpret_cast<float4*>(&b[0]) = *reinterpret_cast<const float4*>(&sB[k * 64 + tn * 4]);
#pragma unroll
            for (int i = 0; i < 4; i++)
#pragma unroll
                for (int j = 0; j < 4; j++) acc[i][j] = fmaf(a[i], b[j], acc[i][j]);
        }
        __syncthreads();
    }

    float bia[4];
    *reinterpret_cast<float4*>(&bia[0]) = *reinterpret_cast<const float4*>(&b_enc[n0e + tn * 4]);
    uint32_t* dhi = reinterpret_cast<uint32_t*>(g_encfhi[s & (ENC_SLOTS - 1)]);
    uint32_t* dlo = reinterpret_cast<uint32_t*>(g_encflo[s & (ENC_SLOTS - 1)]);
#pragma unroll
    for (int i = 0; i < 4; i++) {
        const int row = b0 + tm * 4 + i;
        const int row_tile = row >> 4, rr = row & 15;
        const int r = rr & 7, regbase = rr >> 3;
#pragma unroll
        for (int p = 0; p < 2; p++) {                 // col pair: 4tn+2p, +1
            const int col = n0e + tn * 4 + 2 * p;
            const int chunk = col >> 4, cc = col & 15;
            const int lane = (r << 2) | ((cc & 7) >> 1);
            const int reg = regbase | ((cc >> 3) << 1);
            float v0 = tanhf_(acc[i][2 * p]     + bia[2 * p]);
            float v1 = tanhf_(acc[i][2 * p + 1] + bia[2 * p + 1]);
            unsigned short h0, l0, h1, l1;
            split_bf16(v0, h0, l0);
            split_bf16(v1, h1, l1);
            size_t idx = ((((size_t)row_tile * 16 + chunk) * 32 + lane) << 2) + reg;
            dhi[idx] = (uint32_t)h0 | ((uint32_t)h1 << 16);
            dlo[idx] = (uint32_t)l0 | ((uint32_t)l1 << 16);
        }
    }
}

// ---------------- the fused persistent HMMA kernel (K-split, 8 warps) -------
__global__ void __launch_bounds__(NTHR, 1) lstm_hmma_kernel(
    const float* __restrict__ x, const float* __restrict__ W_enc,
    const float* __restrict__ b_enc, const float* __restrict__ W_x,
    const float* __restrict__ W_h, const float* __restrict__ b_lstm,
    const float* __restrict__ W_dec, const float* __restrict__ b_dec,
    float* __restrict__ out)
{
    extern __shared__ char smem[];
    const int tid = threadIdx.x;
    const int bid = blockIdx.x;
    const int lane = tid & 31;
    const int wid = tid >> 5;
    const int w4 = wid & 3;              // row slice within group
    const int wg = wid >> 2;             // K-split group (0 or 1)
    const int jb = bid & 31;             // gate tile (16 latent cols) == h chunk
    const int mb = bid >> 5;             // batch tile (64 rows)
    const int m0 = mb * 64, j0 = jb * 16;
    const int row_tile = 4 * mb + w4;    // this warp's 16-row group (0..15)
    const uint32_t smem_u = s2u(smem);
    float* biasS = reinterpret_cast<float*>(smem + SM_BIAS);
    float4* zRed = reinterpret_cast<float4*>(smem + SM_ZRED);  // [4][8][32]

    // ---- fill weight slices (bf16 hi/lo, [n][k] rows, XOR-swizzled) ----
    for (int idx = tid; idx < 64 * 512; idx += NTHR) {
        int n = idx >> 9, k = idx & 511;
        float w = W_h[(size_t)k * GG + (n >> 4) * DLAT + j0 + (n & 15)];
        unsigned short sh, sl;
        split_bf16(w, sh, sl);
        uint32_t off = (uint32_t)(n * 1024 + ((2 * k) ^ ((n & 7) << 4)));
        *reinterpret_cast<unsigned short*>(smem + SM_WHI + off) = sh;
        *reinterpret_cast<unsigned short*>(smem + SM_WLO + off) = sl;
    }
    for (int idx = tid; idx < 64 * 256; idx += NTHR) {
        int n = idx >> 8, k = idx & 255;
        float w = W_x[(size_t)k * GG + (n >> 4) * DLAT + j0 + (n & 15)];
        unsigned short sh, sl;
        split_bf16(w, sh, sl);
        uint32_t off = (uint32_t)(n * 512 + ((2 * k) ^ ((n & 7) << 4)));
        *reinterpret_cast<unsigned short*>(smem + SM_XHI + off) = sh;
        *reinterpret_cast<unsigned short*>(smem + SM_XLO + off) = sl;
    }
    if (tid < 64) biasS[tid] = b_lstm[(tid >> 4) * DLAT + j0 + (tid & 15)];

    // ---- per-lane geometry ----
    const int lm = lane >> 3, lr = lane & 7;
    const int koff = (lm & 1) * 16;                    // B klow/khigh select
    const int swz = lr << 4;                           // B swizzle
    uint32_t bW_hi[4], bW_lo[4], bX_hi[4], bX_lo[4];
#pragma unroll
    for (int p = 0; p < 4; p++) {
        int n = 16 * p + 8 * (lm >> 1) + lr;
        bW_hi[p] = smem_u + SM_WHI + n * 1024;
        bW_lo[p] = smem_u + SM_WLO + n * 1024;
        bX_hi[p] = smem_u + SM_XHI + n * 512;
        bX_lo[p] = smem_u + SM_XLO + n * 512;
    }
    const int jc = 2 * (lane & 3);

    // fragment pointers (this warp's row_tile, group chunk base, lane)
    const int hCB = 16 * wg;             // recurrent chunk base for this group
    const int xCB = 8 * wg;              // xz chunk base
    const uint4* hA0  = g_hfhi[0] + ((size_t)row_tile * 32 + hCB) * 32 + lane;
    const uint4* hA0l = g_hflo[0] + ((size_t)row_tile * 32 + hCB) * 32 + lane;
    const uint4* hA1  = g_hfhi[1] + ((size_t)row_tile * 32 + hCB) * 32 + lane;
    const uint4* hA1l = g_hflo[1] + ((size_t)row_tile * 32 + hCB) * 32 + lane;
    const size_t encOff = ((size_t)row_tile * 16 + xCB) * 32 + lane;
    const size_t hStoreIdx = ((size_t)row_tile * 32 + jb) * 32 + lane;

    unsigned gen = *((volatile unsigned*)&g_bar_gen);
    float cReg[8];
#pragma unroll
    for (int i = 0; i < 8; i++) cReg[i] = 0.0f;
    float acc[8][4];

    // xz(t1) partial into acc (this group's chunk half)
    auto xz_partial = [&](int t1) {
        const int slot = t1 & (ENC_SLOTS - 1);
#pragma unroll
        for (int i = 0; i < 8; i++)
#pragma unroll
            for (int j = 0; j < 4; j++) acc[i][j] = 0.0f;
        mma_accF<8>(acc, g_encfhi[slot] + encOff, g_encflo[slot] + encOff,
                    bX_hi, bX_lo, xCB, koff, swz);
    };

    // combine + gates + h-store (wg0 only)
    auto epilogue = [&](int t) {
#pragma unroll
        for (int nt = 0; nt < 8; nt++) {
            float4 v = zRed[(w4 * 8 + nt) * 32 + lane];
            acc[nt][0] += v.x; acc[nt][1] += v.y;
            acc[nt][2] += v.z; acc[nt][3] += v.w;
        }
        uint32_t RH[4], RL[4];
#pragma unroll
        for (int jhi = 0; jhi < 2; jhi++) {
#pragma unroll
            for (int rs = 0; rs < 2; rs++) {
                uint32_t packH = 0, packL = 0;
#pragma unroll
                for (int je = 0; je < 2; je++) {
                    const int j = 8 * jhi + jc + je;
                    float zi = acc[0 + jhi][2 * rs + je] + biasS[j];
                    float zf = acc[2 + jhi][2 * rs + je] + biasS[16 + j];
                    float zg = acc[4 + jhi][2 * rs + je] + biasS[32 + j];
                    float zo = acc[6 + jhi][2 * rs + je] + biasS[48 + j];
                    float ig = sigmoidf_(zi), fg = sigmoidf_(zf);
                    float gg = tanhf_(zg),   og = sigmoidf_(zo);
                    const int ci = rs * 4 + jhi * 2 + je;
                    float cn = fg * cReg[ci] + ig * gg;
                    cReg[ci] = cn;
                    float hv = og * tanhf_(cn);
                    unsigned short sh, sl;
                    split_bf16(hv, sh, sl);
                    packH |= (uint32_t)sh << (16 * je);
                    packL |= (uint32_t)sl << (16 * je);
                }
                RH[rs + 2 * jhi] = packH;
                RL[rs + 2 * jhi] = packL;
            }
        }
        uint4* oh = g_hfhi[(t + 1) & 1] + hStoreIdx;
        uint4* ol = g_hflo[(t + 1) & 1] + hStoreIdx;
        *oh = make_uint4(RH[0], RH[1], RH[2], RH[3]);
        *ol = make_uint4(RL[0], RL[1], RL[2], RL[3]);
    };

    // ---- prologue: enc slots [0,16); barrier; xz(0) partials ----
    __syncthreads();                                   // weights/bias visible
    enc_phase(smem, x, W_enc, b_enc, 0, bid, tid);
    enc_phase(smem, x, W_enc, b_enc, 8, bid, tid);
    __syncthreads();
    if (tid == 0) bar_arrive(gen);
    if (tid == 0) bar_spin(gen);
    gen++;
    __syncthreads();
    xz_partial(0);

    // ---- main scan ----
#pragma unroll 1
    for (int t = 0; t < TT; t++) {
        // recurrent partial: acc += h(t) @ W_h[group k half]  (skip t=0)
        if (t > 0) {
            const uint4* ah = (t & 1) ? hA1 : hA0;
            const uint4* al = (t & 1) ? hA1l : hA0l;
            mma_accF<16>(acc, ah, al, bW_hi, bW_lo, hCB, koff, swz);
        }

        // K-split reduction: group1 publishes partials
        if (wg == 1) {
#pragma unroll
            for (int nt = 0; nt < 8; nt++)
                zRed[(w4 * 8 + nt) * 32 + lane] =
                    make_float4(acc[nt][0], acc[nt][1], acc[nt][2], acc[nt][3]);
        }
        __syncthreads();

        const bool isEnc = ((t & 7) == 0);
        // wg0: combine + epilogue.  wg1 (non-enc steps): xz(t+1) NOW,
        // overlapping wg0's epilogue (xz touches neither zRed nor h).
        if (wg == 0) {
            epilogue(t);
        } else if (!isEnc && t + 1 < TT) {
            xz_partial(t + 1);
        }

        // ARRIVE EARLY: h(t+1) stored; enc + wg0-xz below overlap the barrier
        __syncthreads();
        if (tid == 0) bar_arrive(gen);

        // encoder lookahead (all threads; acc dead for everyone on enc steps)
        if (isEnc && t + 16 < TT)
            enc_phase(smem, x, W_enc, b_enc, t + 16, bid, tid);

        // xz(t+1): wg0 always here (barrier shadow); wg1 only on enc steps
        if (t + 1 < TT && (wg == 0 || isEnc))
            xz_partial(t + 1);

        // WAIT: h(t+1) visible everywhere before next recurrent GEMM
        if (tid == 0) bar_spin(gen);
        gen++;
        __syncthreads();
    }

    // ---- decoder: out[b] = h_last @ W_dec + b_dec (h_last in buf 0) ----
    if (jb == 0 && tid < 64) {
        const int row = m0 + tid;
        const int rt2 = row >> 4, rr = row & 15;
        const int r = rr & 7, regbase = rr >> 3;
        const uint32_t* hh = reinterpret_cast<const uint32_t*>(g_hfhi[0]);
        const uint32_t* hl = reinterpret_cast<const uint32_t*>(g_hflo[0]);
        float s = 0.0f;
        for (int k = 0; k < DLAT; k++) {
            const int chunk = k >> 4, cc = k & 15;
            const int ln = (r << 2) | ((cc & 7) >> 1);
            const int reg = regbase | ((cc >> 3) << 1);
            size_t idx = ((((size_t)rt2 * 32 + chunk) * 32 + ln) << 2) + reg;
            const int shf = (cc & 1) * 16;
            float hv = b2f(hh[idx] >> shf) + b2f(hl[idx] >> shf);
            s = fmaf(hv, W_dec[k], s);
        }
        out[row] = s + b_dec[0];
    }
}

// ---------------- eager module touch ----------------
namespace {
struct EagerLoad {
    EagerLoad() {
        void* p;
        cudaGetSymbolAddress(&p, g_encfhi);
        cudaGetSymbolAddress(&p, g_encflo);
        cudaGetSymbolAddress(&p, g_hfhi);
        cudaGetSymbolAddress(&p, g_hflo);
        cudaGetSymbolAddress(&p, g_bar_cnt);
        cudaFuncSetAttribute(lstm_hmma_kernel,
                             cudaFuncAttributeMaxDynamicSharedMemorySize, SM_TOTAL);
    }
};
EagerLoad eager_load_instance;
}  // namespace

// ---------------- launch ----------------
extern "C" void kernel_launch(void* const* d_in, const int* in_sizes, int n_in,
                              void* d_out, int out_size)
{
    const float* x      = (const float*)d_in[0];
    const float* W_enc  = (const float*)d_in[1];
    const float* b_enc  = (const float*)d_in[2];
    const float* W_x    = (const float*)d_in[3];
    const float* W_h    = (const float*)d_in[4];
    const float* b_lstm = (const float*)d_in[5];
    const float* W_dec  = (const float*)d_in[6];
    const float* b_dec  = (const float*)d_in[7];
    float* out = (float*)d_out;

    cudaFuncSetAttribute(lstm_hmma_kernel,
                         cudaFuncAttributeMaxDynamicSharedMemorySize, SM_TOTAL);

    lstm_hmma_kernel<<<NBLK, NTHR, SM_TOTAL>>>(
        x, W_enc, b_enc, W_x, W_h, b_lstm, W_dec, b_dec, out);
}

// round 16
// speedup vs baseline: 1.6239x; 1.0037x over previous
#include <cuda_runtime.h>
#include <cuda_bf16.h>
#include <cstdint>

// Problem constants
#define BATCH 256
#define TT    512
#define DIN   128
#define DFEAT 256
#define DLAT  512
#define GG    2048
#define NBLK  128            // 4 batch-tiles x 32 gate-tiles, persistent, 1 CTA/SM
#define NTHR  256            // 8 warps = 2 K-split groups of 4
#define ENC_SLOTS 32

// ---------------- device-global scratch, MMA-fragment layout (~9 MB) --------
// h:   [buf][row_tile(16)][chunk(32)][lane(32)] uint4 {R0,R1,R2,R3}
// enc: [slot][row_tile(16)][chunk(16)][lane(32)] uint4
__device__ uint4 g_hfhi[2][16 * 32 * 32];            // 256 KB / buf
__device__ uint4 g_hflo[2][16 * 32 * 32];
__device__ uint4 g_encfhi[ENC_SLOTS][16 * 16 * 32];  // 4 MB
__device__ uint4 g_encflo[ENC_SLOTS][16 * 16 * 32];
__device__ unsigned g_bar_cnt;
__device__ unsigned g_bar_gen;

// ---------------- smem layout (bytes) ----------------
#define SM_WHI  0                        // W_h hi  [64 n][512 k] bf16, row=1024B
#define SM_WLO  65536
#define SM_XHI  131072                   // W_x hi  [64 n][256 k] bf16, row=512B
#define SM_XLO  163840
#define SM_ENC  196608                   // enc staging: hA 16*68 f32 + sB 16*64 f32 = 8448
#define SM_ZRED (SM_ENC + 8448)          // K-split reduction [4][8][32] float4 = 16384
#define SM_BIAS (SM_ZRED + 16384)        // 64 floats
#define SM_TOTAL (SM_BIAS + 256)         // 221,696 B

// ---------------- math ----------------
__device__ __forceinline__ float sigmoidf_(float x) { return 1.0f / (1.0f + __expf(-x)); }
__device__ __forceinline__ float tanhf_(float x) {
    x = fminf(fmaxf(x, -12.0f), 12.0f);
    float e = __expf(2.0f * x);
    return (e - 1.0f) / (e + 1.0f);
}
__device__ __forceinline__ float b2f(uint32_t u) {
    unsigned short s = (unsigned short)u;
    __nv_bfloat16 b = *reinterpret_cast<__nv_bfloat16*>(&s);
    return __bfloat162float(b);
}

// ---------------- split-phase central barrier (128 co-resident CTAs) --------
__device__ __forceinline__ void bar_arrive(unsigned gen) {
    __threadfence();
    unsigned arrived = atomicAdd(&g_bar_cnt, 1u);
    if (arrived == NBLK - 1) {
        atomicExch(&g_bar_cnt, 0u);
        __threadfence();
        *((volatile unsigned*)&g_bar_gen) = gen + 1u;
    }
}
__device__ __forceinline__ void bar_spin(unsigned gen) {
    while (*((volatile unsigned*)&g_bar_gen) == gen) { __nanosleep(32); }
    __threadfence();
}

// ---------------- PTX helpers (baseline PTX, sm_80-era) ----------------
__device__ __forceinline__ uint32_t s2u(const void* p) {
    uint32_t a;
    asm("{ .reg .u64 t; cvta.to.shared.u64 t, %1; cvt.u32.u64 %0, t; }" : "=r"(a) : "l"(p));
    return a;
}
__device__ __forceinline__ void ldsm4(uint32_t& r0, uint32_t& r1, uint32_t& r2, uint32_t& r3,
                                      uint32_t addr) {
    asm volatile("ldmatrix.sync.aligned.m8n8.x4.shared.b16 {%0,%1,%2,%3}, [%4];"
                 : "=r"(r0), "=r"(r1), "=r"(r2), "=r"(r3) : "r"(addr));
}
__device__ __forceinline__ void mma4(float* d, const uint32_t* a, const uint32_t* b) {
    asm volatile(
        "mma.sync.aligned.m16n8k16.row.col.f32.bf16.bf16.f32 "
        "{%0,%1,%2,%3}, {%4,%5,%6,%7}, {%8,%9}, {%0,%1,%2,%3};"
        : "+f"(d[0]), "+f"(d[1]), "+f"(d[2]), "+f"(d[3])
        : "r"(a[0]), "r"(a[1]), "r"(a[2]), "r"(a[3]), "r"(b[0]), "r"(b[1]));
}

// ---------------- hi/lo split helper ----------------
__device__ __forceinline__ void split_bf16(float v, unsigned short& hi, unsigned short& lo) {
    __nv_bfloat16 h16 = __float2bfloat16(v);
    __nv_bfloat16 l16 = __float2bfloat16(v - __bfloat162float(h16));
    hi = __bfloat16_as_ushort(h16);
    lo = __bfloat16_as_ushort(l16);
}

// ---------------- MMA accumulate, fragment-layout A, QUAD-buffered A --------
// acc += A(frag global hi/lo) @ B(smem hi/lo). NCH chunks (multiple of 4).
// A prefetch distance 4; B double-buffered (smem).
// 3-pass, PASS-MAJOR issue order: all AhiBhi, all AhiBlo, all AloBhi —
// same-accumulator reuse distance = 8 instructions (covers HMMA latency).
// Per-accumulator addition order unchanged -> bit-identical results.
template<int NCH>
__device__ __forceinline__ void mma_accF(
    float (&acc)[8][4],
    const uint4* __restrict__ aHiT, const uint4* __restrict__ aLoT,
    const uint32_t* bHiA, const uint32_t* bLoA,
    int cbase, int koff, int swz)
{
    uint32_t aH[4][4], aL[4][4];
    uint32_t bh[2][8][2], bl[2][8][2];

    auto loadA = [&](int buf, int c) {
        uint4 vh = aHiT[c * 32];
        uint4 vl = aLoT[c * 32];
        aH[buf][0] = vh.x; aH[buf][1] = vh.y; aH[buf][2] = vh.z; aH[buf][3] = vh.w;
        aL[buf][0] = vl.x; aL[buf][1] = vl.y; aL[buf][2] = vl.z; aL[buf][3] = vl.w;
    };
    auto loadB = [&](int buf, int c) {
        const int off = ((cbase + c) * 32 + koff) ^ swz;
#pragma unroll
        for (int p = 0; p < 4; p++) {
            ldsm4(bh[buf][2 * p][0], bh[buf][2 * p][1],
                  bh[buf][2 * p + 1][0], bh[buf][2 * p + 1][1], bHiA[p] + off);
            ldsm4(bl[buf][2 * p][0], bl[buf][2 * p][1],
                  bl[buf][2 * p + 1][0], bl[buf][2 * p + 1][1], bLoA[p] + off);
        }
    };
    auto doMMA = [&](int buf, int bbuf) {
#pragma unroll
        for (int nt = 0; nt < 8; nt++) mma4(acc[nt], aH[buf], bh[bbuf][nt]);
#pragma unroll
        for (int nt = 0; nt < 8; nt++) mma4(acc[nt], aH[buf], bl[bbuf][nt]);
#pragma unroll
        for (int nt = 0; nt < 8; nt++) mma4(acc[nt], aL[buf], bh[bbuf][nt]);
    };

    loadA(0, 0); loadA(1, 1); loadA(2, 2); loadA(3, 3);
    loadB(0, 0);
#pragma unroll 1
    for (int c = 0; c < NCH; c += 4) {
        loadB(1, c + 1);
        doMMA(0, 0);                         // chunk c
        if (c + 4 < NCH) loadA(0, c + 4);    // refill AFTER consumption, dist 4
        loadB(0, c + 2);
        doMMA(1, 1);                         // chunk c+1
        if (c + 5 < NCH) loadA(1, c + 5);
        loadB(1, c + 3);
        doMMA(2, 0);                         // chunk c+2
        if (c + 6 < NCH) loadA(2, c + 6);
        if (c + 4 < NCH) loadB(0, c + 4);
        doMMA(3, 1);                         // chunk c+3
        if (c + 7 < NCH) loadA(3, c + 7);
    }
}

// ---------------- encoder FFMA phase (amortized /8 steps, 128 CTAs x 256 thr)
// 128 CTAs cover 8 timesteps x 4 batch-tiles(64) x 4 col-tiles(64). K=128.
// Output goes to the enc FRAGMENT layout.
__device__ void enc_phase(
    char* smem, const float* __restrict__ x, const float* __restrict__ W_enc,
    const float* __restrict__ b_enc, int sbase, int bid, int tid)
{
    const int q = bid >> 2;
    const int s = sbase + (q >> 2);
    if (s >= TT) return;
    const int b0  = (q & 3) * 64;
    const int n0e = (bid & 3) * 64;
    const int tn = tid & 15, tm = tid >> 4;            // tm 0..15 (4 rows each)
    float* hA = reinterpret_cast<float*>(smem + SM_ENC);         // [16][68]
    float* sB = hA + 16 * 68;                                    // [16][64]

    float acc[4][4];
#pragma unroll
    for (int i = 0; i < 4; i++)
#pragma unroll
        for (int j = 0; j < 4; j++) acc[i][j] = 0.0f;

#pragma unroll 1
    for (int k0 = 0; k0 < DIN; k0 += 16) {
        {   // A^T: 64 rows x 16 k = 256 float4, one per thread
            int row = tid >> 2, kq = tid & 3;
            float4 v = *reinterpret_cast<const float4*>(
                &x[(size_t)(b0 + row) * TT * DIN + (size_t)s * DIN + k0 + kq * 4]);
            hA[(kq * 4 + 0) * 68 + row] = v.x; hA[(kq * 4 + 1) * 68 + row] = v.y;
            hA[(kq * 4 + 2) * 68 + row] = v.z; hA[(kq * 4 + 3) * 68 + row] = v.w;
        }
        {   // B: 16 x 64 = 256 float4, one per thread
            int kr = tid >> 4, nq = tid & 15;
            float4 v = *reinterpret_cast<const float4*>(
                &W_enc[(size_t)(k0 + kr) * DFEAT + n0e + nq * 4]);
            *reinterpret_cast<float4*>(&sB[kr * 64 + nq * 4]) = v;
        }
        __syncthreads();
#pragma unroll
        for (int k = 0; k < 16; k++) {
            float a[4], b[4];
            *reinterpret_cast<float4*>(&a[0]) = *reinterpret_cast<const float4*>(&hA[k * 68 + tm * 4]);
            *reinterpret_cast<float4*>(&b[0]) = *reinterpret_cast<const float4*>(&sB[k * 64 + tn * 4]);
#pragma unroll
            for (int i = 0; i < 4; i++)
#pragma unroll
                for (int j = 0; j < 4; j++) acc[i][j] = fmaf(a[i], b[j], acc[i][j]);
        }
        __syncthreads();
    }

    float bia[4];
    *reinterpret_cast<float4*>(&bia[0]) = *reinterpret_cast<const float4*>(&b_enc[n0e + tn * 4]);
    uint32_t* dhi = reinterpret_cast<uint32_t*>(g_encfhi[s & (ENC_SLOTS - 1)]);
    uint32_t* dlo = reinterpret_cast<uint32_t*>(g_encflo[s & (ENC_SLOTS - 1)]);
#pragma unroll
    for (int i = 0; i < 4; i++) {
        const int row = b0 + tm * 4 + i;
        const int row_tile = row >> 4, rr = row & 15;
        const int r = rr & 7, regbase = rr >> 3;
#pragma unroll
        for (int p = 0; p < 2; p++) {                 // col pair: 4tn+2p, +1
            const int col = n0e + tn * 4 + 2 * p;
            const int chunk = col >> 4, cc = col & 15;
            const int lane = (r << 2) | ((cc & 7) >> 1);
            const int reg = regbase | ((cc >> 3) << 1);
            float v0 = tanhf_(acc[i][2 * p]     + bia[2 * p]);
            float v1 = tanhf_(acc[i][2 * p + 1] + bia[2 * p + 1]);
            unsigned short h0, l0, h1, l1;
            split_bf16(v0, h0, l0);
            split_bf16(v1, h1, l1);
            size_t idx = ((((size_t)row_tile * 16 + chunk) * 32 + lane) << 2) + reg;
            dhi[idx] = (uint32_t)h0 | ((uint32_t)h1 << 16);
            dlo[idx] = (uint32_t)l0 | ((uint32_t)l1 << 16);
        }
    }
}

// ---------------- the fused persistent HMMA kernel (K-split, 8 warps) -------
__global__ void __launch_bounds__(NTHR, 1) lstm_hmma_kernel(
    const float* __restrict__ x, const float* __restrict__ W_enc,
    const float* __restrict__ b_enc, const float* __restrict__ W_x,
    const float* __restrict__ W_h, const float* __restrict__ b_lstm,
    const float* __restrict__ W_dec, const float* __restrict__ b_dec,
    float* __restrict__ out)
{
    extern __shared__ char smem[];
    const int tid = threadIdx.x;
    const int bid = blockIdx.x;
    const int lane = tid & 31;
    const int wid = tid >> 5;
    const int w4 = wid & 3;              // row slice within group
    const int wg = wid >> 2;             // K-split group (0 or 1)
    const int jb = bid & 31;             // gate tile (16 latent cols) == h chunk
    const int mb = bid >> 5;             // batch tile (64 rows)
    const int m0 = mb * 64, j0 = jb * 16;
    const int row_tile = 4 * mb + w4;    // this warp's 16-row group (0..15)
    const uint32_t smem_u = s2u(smem);
    float* biasS = reinterpret_cast<float*>(smem + SM_BIAS);
    float4* zRed = reinterpret_cast<float4*>(smem + SM_ZRED);  // [4][8][32]

    // ---- fill weight slices (bf16 hi/lo, [n][k] rows, XOR-swizzled) ----
    for (int idx = tid; idx < 64 * 512; idx += NTHR) {
        int n = idx >> 9, k = idx & 511;
        float w = W_h[(size_t)k * GG + (n >> 4) * DLAT + j0 + (n & 15)];
        unsigned short sh, sl;
        split_bf16(w, sh, sl);
        uint32_t off = (uint32_t)(n * 1024 + ((2 * k) ^ ((n & 7) << 4)));
        *reinterpret_cast<unsigned short*>(smem + SM_WHI + off) = sh;
        *reinterpret_cast<unsigned short*>(smem + SM_WLO + off) = sl;
    }
    for (int idx = tid; idx < 64 * 256; idx += NTHR) {
        int n = idx >> 8, k = idx & 255;
        float w = W_x[(size_t)k * GG + (n >> 4) * DLAT + j0 + (n & 15)];
        unsigned short sh, sl;
        split_bf16(w, sh, sl);
        uint32_t off = (uint32_t)(n * 512 + ((2 * k) ^ ((n & 7) << 4)));
        *reinterpret_cast<unsigned short*>(smem + SM_XHI + off) = sh;
        *reinterpret_cast<unsigned short*>(smem + SM_XLO + off) = sl;
    }
    if (tid < 64) biasS[tid] = b_lstm[(tid >> 4) * DLAT + j0 + (tid & 15)];

    // ---- per-lane geometry ----
    const int lm = lane >> 3, lr = lane & 7;
    const int koff = (lm & 1) * 16;                    // B klow/khigh select
    const int swz = lr << 4;                           // B swizzle
    uint32_t bW_hi[4], bW_lo[4], bX_hi[4], bX_lo[4];
#pragma unroll
    for (int p = 0; p < 4; p++) {
        int n = 16 * p + 8 * (lm >> 1) + lr;
        bW_hi[p] = smem_u + SM_WHI + n * 1024;
        bW_lo[p] = smem_u + SM_WLO + n * 1024;
        bX_hi[p] = smem_u + SM_XHI + n * 512;
        bX_lo[p] = smem_u + SM_XLO + n * 512;
    }
    const int jc = 2 * (lane & 3);

    // fragment pointers (this warp's row_tile, group chunk base, lane)
    const int hCB = 16 * wg;             // recurrent chunk base for this group
    const int xCB = 8 * wg;              // xz chunk base
    const uint4* hA0  = g_hfhi[0] + ((size_t)row_tile * 32 + hCB) * 32 + lane;
    const uint4* hA0l = g_hflo[0] + ((size_t)row_tile * 32 + hCB) * 32 + lane;
    const uint4* hA1  = g_hfhi[1] + ((size_t)row_tile * 32 + hCB) * 32 + lane;
    const uint4* hA1l = g_hflo[1] + ((size_t)row_tile * 32 + hCB) * 32 + lane;
    const size_t encOff = ((size_t)row_tile * 16 + xCB) * 32 + lane;
    const size_t hStoreIdx = ((size_t)row_tile * 32 + jb) * 32 + lane;

    unsigned gen = *((volatile unsigned*)&g_bar_gen);
    float cReg[8];
#pragma unroll
    for (int i = 0; i < 8; i++) cReg[i] = 0.0f;
    float acc[8][4];

    // xz(t1) partial into acc (this group's chunk half)
    auto xz_partial = [&](int t1) {
        const int slot = t1 & (ENC_SLOTS - 1);
#pragma unroll
        for (int i = 0; i < 8; i++)
#pragma unroll
            for (int j = 0; j < 4; j++) acc[i][j] = 0.0f;
        mma_accF<8>(acc, g_encfhi[slot] + encOff, g_encflo[slot] + encOff,
                    bX_hi, bX_lo, xCB, koff, swz);
    };

    // combine + gates + h-store (wg0 only)
    auto epilogue = [&](int t) {
#pragma unroll
        for (int nt = 0; nt < 8; nt++) {
            float4 v = zRed[(w4 * 8 + nt) * 32 + lane];
            acc[nt][0] += v.x; acc[nt][1] += v.y;
            acc[nt][2] += v.z; acc[nt][3] += v.w;
        }
        uint32_t RH[4], RL[4];
#pragma unroll
        for (int jhi = 0; jhi < 2; jhi++) {
#pragma unroll
            for (int rs = 0; rs < 2; rs++) {
                uint32_t packH = 0, packL = 0;
#pragma unroll
                for (int je = 0; je < 2; je++) {
                    const int j = 8 * jhi + jc + je;
                    float zi = acc[0 + jhi][2 * rs + je] + biasS[j];
                    float zf = acc[2 + jhi][2 * rs + je] + biasS[16 + j];
                    float zg = acc[4 + jhi][2 * rs + je] + biasS[32 + j];
                    float zo = acc[6 + jhi][2 * rs + je] + biasS[48 + j];
                    float ig = sigmoidf_(zi), fg = sigmoidf_(zf);
                    float gg = tanhf_(zg),   og = sigmoidf_(zo);
                    const int ci = rs * 4 + jhi * 2 + je;
                    float cn = fg * cReg[ci] + ig * gg;
                    cReg[ci] = cn;
                    float hv = og * tanhf_(cn);
                    unsigned short sh, sl;
                    split_bf16(hv, sh, sl);
                    packH |= (uint32_t)sh << (16 * je);
                    packL |= (uint32_t)sl << (16 * je);
                }
                RH[rs + 2 * jhi] = packH;
                RL[rs + 2 * jhi] = packL;
            }
        }
        uint4* oh = g_hfhi[(t + 1) & 1] + hStoreIdx;
        uint4* ol = g_hflo[(t + 1) & 1] + hStoreIdx;
        *oh = make_uint4(RH[0], RH[1], RH[2], RH[3]);
        *ol = make_uint4(RL[0], RL[1], RL[2], RL[3]);
    };

    // ---- prologue: enc slots [0,16); barrier; xz(0) partials ----
    __syncthreads();                                   // weights/bias visible
    enc_phase(smem, x, W_enc, b_enc, 0, bid, tid);
    enc_phase(smem, x, W_enc, b_enc, 8, bid, tid);
    __syncthreads();
    if (tid == 0) bar_arrive(gen);
    if (tid == 0) bar_spin(gen);
    gen++;
    __syncthreads();
    xz_partial(0);

    // ---- main scan ----
#pragma unroll 1
    for (int t = 0; t < TT; t++) {
        // recurrent partial: acc += h(t) @ W_h[group k half]  (skip t=0)
        if (t > 0) {
            const uint4* ah = (t & 1) ? hA1 : hA0;
            const uint4* al = (t & 1) ? hA1l : hA0l;
            mma_accF<16>(acc, ah, al, bW_hi, bW_lo, hCB, koff, swz);
        }

        // K-split reduction: group1 publishes partials
        if (wg == 1) {
#pragma unroll
            for (int nt = 0; nt < 8; nt++)
                zRed[(w4 * 8 + nt) * 32 + lane] =
                    make_float4(acc[nt][0], acc[nt][1], acc[nt][2], acc[nt][3]);
        }
        __syncthreads();

        const bool isEnc = ((t & 7) == 0);
        // wg0: combine + epilogue, then wg0-ONLY barrier + arrive — does NOT
        // wait for wg1's xz. wg1 (non-enc steps): xz(t+1) immediately.
        if (wg == 0) {
            epilogue(t);
            asm volatile("bar.sync 1, 128;" ::: "memory");   // wg0 h-stores done
            if (tid == 0) bar_arrive(gen);
        } else if (!isEnc && t + 1 < TT) {
            xz_partial(t + 1);
        }

        // encoder lookahead (all threads; acc dead for everyone on enc steps)
        if (isEnc && t + 16 < TT)
            enc_phase(smem, x, W_enc, b_enc, t + 16, bid, tid);

        // xz(t+1): wg0 always here (barrier shadow); wg1 only on enc steps
        if (t + 1 < TT && (wg == 0 || isEnc))
            xz_partial(t + 1);

        // WAIT: h(t+1) visible everywhere before next recurrent GEMM.
        // Loop-end __syncthreads also separates wg0's zRed reads (epilogue)
        // from wg1's next-step publish.
        if (tid == 0) bar_spin(gen);
        gen++;
        __syncthreads();
    }

    // ---- decoder: out[b] = h_last @ W_dec + b_dec (h_last in buf 0) ----
    if (jb == 0 && tid < 64) {
        const int row = m0 + tid;
        const int rt2 = row >> 4, rr = row & 15;
        const int r = rr & 7, regbase = rr >> 3;
        const uint32_t* hh = reinterpret_cast<const uint32_t*>(g_hfhi[0]);
        const uint32_t* hl = reinterpret_cast<const uint32_t*>(g_hflo[0]);
        float s = 0.0f;
        for (int k = 0; k < DLAT; k++) {
            const int chunk = k >> 4, cc = k & 15;
            const int ln = (r << 2) | ((cc & 7) >> 1);
            const int reg = regbase | ((cc >> 3) << 1);
            size_t idx = ((((size_t)rt2 * 32 + chunk) * 32 + ln) << 2) + reg;
            const int shf = (cc & 1) * 16;
            float hv = b2f(hh[idx] >> shf) + b2f(hl[idx] >> shf);
            s = fmaf(hv, W_dec[k], s);
        }
        out[row] = s + b_dec[0];
    }
}

// ---------------- eager module touch ----------------
namespace {
struct EagerLoad {
    EagerLoad() {
        void* p;
        cudaGetSymbolAddress(&p, g_encfhi);
        cudaGetSymbolAddress(&p, g_encflo);
        cudaGetSymbolAddress(&p, g_hfhi);
        cudaGetSymbolAddress(&p, g_hflo);
        cudaGetSymbolAddress(&p, g_bar_cnt);
        cudaFuncSetAttribute(lstm_hmma_kernel,
                             cudaFuncAttributeMaxDynamicSharedMemorySize, SM_TOTAL);
    }
};
EagerLoad eager_load_instance;
}  // namespace

// ---------------- launch ----------------
extern "C" void kernel_launch(void* const* d_in, const int* in_sizes, int n_in,
                              void* d_out, int out_size)
{
    const float* x      = (const float*)d_in[0];
    const float* W_enc  = (const float*)d_in[1];
    const float* b_enc  = (const float*)d_in[2];
    const float* W_x    = (const float*)d_in[3];
    const float* W_h    = (const float*)d_in[4];
    const float* b_lstm = (const float*)d_in[5];
    const float* W_dec  = (const float*)d_in[6];
    const float* b_dec  = (const float*)d_in[7];
    float* out = (float*)d_out;

    cudaFuncSetAttribute(lstm_hmma_kernel,
                         cudaFuncAttributeMaxDynamicSharedMemorySize, SM_TOTAL);

    lstm_hmma_kernel<<<NBLK, NTHR, SM_TOTAL>>>(
        x, W_enc, b_enc, W_x, W_h, b_lstm, W_dec, b_dec, out);
}